// round 3
// baseline (speedup 1.0000x reference)
#include <cuda_runtime.h>

#define BATCH 8
#define SEQ   2048
#define DIN   1024
#define DHEAD 128
#define NROWS (BATCH * SEQ)

// Scratch for projected q/k/v (allocation-free rule: use __device__ globals)
__device__ float g_q[NROWS * DHEAD];
__device__ float g_k[NROWS * DHEAD];
__device__ float g_v[NROWS * DHEAD];

// ---------------------------------------------------------------------------
// Projection GEMM: Y[16384,128] = X[16384,1024] @ W[1024,128] + b
// (unchanged from R2 — runs at ~72% of fp32 FFMA roofline)
// ---------------------------------------------------------------------------
__global__ __launch_bounds__(256) void proj_kernel(
    const float* __restrict__ Xq, const float* __restrict__ Xk, const float* __restrict__ Xv,
    const float* __restrict__ Wq, const float* __restrict__ Wk, const float* __restrict__ Wv,
    const float* __restrict__ bq, const float* __restrict__ bk, const float* __restrict__ bv)
{
    const float* X;
    const float* W;
    const float* bias;
    float* Y;
    if (blockIdx.y == 0)      { X = Xq; W = Wq; bias = bq; Y = g_q; }
    else if (blockIdx.y == 1) { X = Xk; W = Wk; bias = bk; Y = g_k; }
    else                      { X = Xv; W = Wv; bias = bv; Y = g_v; }

    __shared__ float As[16][64];
    __shared__ float Bs[16][128];

    const int row0 = blockIdx.x * 64;
    const int t  = threadIdx.x;
    const int ty = t >> 4;
    const int tx = t & 15;

    float acc[4][8];
#pragma unroll
    for (int i = 0; i < 4; i++)
#pragma unroll
        for (int j = 0; j < 8; j++) acc[i][j] = 0.f;

    const int ar = t >> 2;
    const int ak = (t & 3) << 2;
    const int bn = (t & 31) << 2;
    const int bk0 = t >> 5;

    for (int k0 = 0; k0 < DIN; k0 += 16) {
        float4 a4  = *reinterpret_cast<const float4*>(X + (size_t)(row0 + ar) * DIN + k0 + ak);
        float4 b4a = *reinterpret_cast<const float4*>(W + (size_t)(k0 + bk0) * DHEAD + bn);
        float4 b4b = *reinterpret_cast<const float4*>(W + (size_t)(k0 + 8 + bk0) * DHEAD + bn);

        __syncthreads();
        As[ak + 0][ar] = a4.x;
        As[ak + 1][ar] = a4.y;
        As[ak + 2][ar] = a4.z;
        As[ak + 3][ar] = a4.w;
        *reinterpret_cast<float4*>(&Bs[bk0][bn])     = b4a;
        *reinterpret_cast<float4*>(&Bs[bk0 + 8][bn]) = b4b;
        __syncthreads();

#pragma unroll
        for (int kk = 0; kk < 16; kk++) {
            float4 av  = *reinterpret_cast<const float4*>(&As[kk][ty << 2]);
            float4 bv0 = *reinterpret_cast<const float4*>(&Bs[kk][tx << 3]);
            float4 bv1 = *reinterpret_cast<const float4*>(&Bs[kk][(tx << 3) + 4]);
            float a_[4] = {av.x, av.y, av.z, av.w};
            float b_[8] = {bv0.x, bv0.y, bv0.z, bv0.w, bv1.x, bv1.y, bv1.z, bv1.w};
#pragma unroll
            for (int i = 0; i < 4; i++)
#pragma unroll
                for (int j = 0; j < 8; j++)
                    acc[i][j] += a_[i] * b_[j];
        }
    }

#pragma unroll
    for (int i = 0; i < 4; i++) {
        float* yp = Y + (size_t)(row0 + (ty << 2) + i) * DHEAD + (tx << 3);
#pragma unroll
        for (int j = 0; j < 8; j++)
            yp[j] = acc[i][j] + bias[(tx << 3) + j];
    }
}

// ---------------------------------------------------------------------------
// Flash attention v2: grid (SEQ/64, BATCH), 256 threads, 2 CTAs/SM.
// Thread tile = 2 query rows x 16 dims: K/V fragments reused across 2 rows
// (8 FFMA per LDS.128 instead of 4). 8 lanes per row (p = t&7, dims 16p).
// All row-groups in a warp read the same key row -> broadcast LDS, no skew,
// flat 64x128 K and V tiles (64 KB dynamic smem, 2 CTAs/SM resident).
// Online softmax in 8-key chunks.
// ---------------------------------------------------------------------------
#define KT 64

__global__ __launch_bounds__(256, 2) void attn_kernel(float* __restrict__ O)
{
    extern __shared__ float sm[];
    float* Ks = sm;                 // [64][128]
    float* Vs = sm + KT * DHEAD;    // [64][128]

    const int b   = blockIdx.y;
    const int q0  = blockIdx.x * 64;
    const int t   = threadIdx.x;
    const int rp  = t >> 3;         // 0..31  row-pair index
    const int p   = t & 7;          // 0..7   dim-slice within row
    const int d0  = p << 4;         // dim offset (16 dims per thread)
    const int ra  = (rp << 1);      // row a
    const int rb  = ra + 1;         // row b

    const float scale = 0.088388347648318447f;  // 1/sqrt(128)

    float qa[16], qb[16];
    {
        const float* qpa = g_q + (size_t)(b * SEQ + q0 + ra) * DHEAD + d0;
        const float* qpb = g_q + (size_t)(b * SEQ + q0 + rb) * DHEAD + d0;
#pragma unroll
        for (int i = 0; i < 16; i++) { qa[i] = qpa[i] * scale; qb[i] = qpb[i] * scale; }
    }

    float acca[16], accb[16];
#pragma unroll
    for (int i = 0; i < 16; i++) { acca[i] = 0.f; accb[i] = 0.f; }
    float ma = -1e30f, mb = -1e30f, la = 0.f, lb = 0.f;

    const float* kb_ = g_k + (size_t)b * SEQ * DHEAD;
    const float* vb_ = g_v + (size_t)b * SEQ * DHEAD;

    for (int j0 = 0; j0 < SEQ; j0 += KT) {
        __syncthreads();
        // load K,V tiles: 2048 float4 each, 8 per thread per tile; coalesced,
        // conflict-free STS.128
#pragma unroll
        for (int u = 0; u < 8; u++) {
            int f4 = t + (u << 8);
            int r  = f4 >> 5;
            int c4 = (f4 & 31) << 2;
            *reinterpret_cast<float4*>(Ks + r * DHEAD + c4) =
                *reinterpret_cast<const float4*>(kb_ + (size_t)(j0 + r) * DHEAD + c4);
            *reinterpret_cast<float4*>(Vs + r * DHEAD + c4) =
                *reinterpret_cast<const float4*>(vb_ + (size_t)(j0 + r) * DHEAD + c4);
        }
        __syncthreads();

        for (int c = 0; c < 8; c++) {   // 8-key chunks
            float pa[8], pb[8];
            float ta = -1e30f, tb = -1e30f;
#pragma unroll
            for (int jj = 0; jj < 8; jj++) {
                const float* kr = Ks + ((c << 3) + jj) * DHEAD + d0;
                float sa = 0.f, sb = 0.f;
#pragma unroll
                for (int i = 0; i < 16; i += 4) {
                    float4 kv = *reinterpret_cast<const float4*>(kr + i);
                    sa += qa[i]     * kv.x;  sb += qb[i]     * kv.x;
                    sa += qa[i + 1] * kv.y;  sb += qb[i + 1] * kv.y;
                    sa += qa[i + 2] * kv.z;  sb += qb[i + 2] * kv.z;
                    sa += qa[i + 3] * kv.w;  sb += qb[i + 3] * kv.w;
                }
                // reduce over the 8 lanes of this row (lane bits 0..2)
                sa += __shfl_xor_sync(0xffffffffu, sa, 1);
                sa += __shfl_xor_sync(0xffffffffu, sa, 2);
                sa += __shfl_xor_sync(0xffffffffu, sa, 4);
                sb += __shfl_xor_sync(0xffffffffu, sb, 1);
                sb += __shfl_xor_sync(0xffffffffu, sb, 2);
                sb += __shfl_xor_sync(0xffffffffu, sb, 4);
                pa[jj] = sa;  pb[jj] = sb;
                ta = fmaxf(ta, sa);  tb = fmaxf(tb, sb);
            }

            float mna = fmaxf(ma, ta), mnb = fmaxf(mb, tb);
            float aa  = __expf(ma - mna), ab = __expf(mb - mnb);
            ma = mna;  mb = mnb;
            float lsa = 0.f, lsb = 0.f;
#pragma unroll
            for (int jj = 0; jj < 8; jj++) {
                pa[jj] = __expf(pa[jj] - mna);  lsa += pa[jj];
                pb[jj] = __expf(pb[jj] - mnb);  lsb += pb[jj];
            }
            la = la * aa + lsa;
            lb = lb * ab + lsb;
#pragma unroll
            for (int i = 0; i < 16; i++) { acca[i] *= aa; accb[i] *= ab; }

#pragma unroll
            for (int jj = 0; jj < 8; jj++) {
                const float* vr = Vs + ((c << 3) + jj) * DHEAD + d0;
                float wa = pa[jj], wb = pb[jj];
#pragma unroll
                for (int i = 0; i < 16; i += 4) {
                    float4 vv = *reinterpret_cast<const float4*>(vr + i);
                    acca[i]     += wa * vv.x;  accb[i]     += wb * vv.x;
                    acca[i + 1] += wa * vv.y;  accb[i + 1] += wb * vv.y;
                    acca[i + 2] += wa * vv.z;  accb[i + 2] += wb * vv.z;
                    acca[i + 3] += wa * vv.w;  accb[i + 3] += wb * vv.w;
                }
            }
        }
    }

    const float inva = 1.f / la;
    const float invb = 1.f / lb;
    float* opa = O + (size_t)(b * SEQ + q0 + ra) * DHEAD + d0;
    float* opb = O + (size_t)(b * SEQ + q0 + rb) * DHEAD + d0;
#pragma unroll
    for (int i = 0; i < 16; i += 4) {
        float4 oa = {acca[i] * inva, acca[i+1] * inva, acca[i+2] * inva, acca[i+3] * inva};
        float4 ob = {accb[i] * invb, accb[i+1] * invb, accb[i+2] * invb, accb[i+3] * invb};
        *reinterpret_cast<float4*>(opa + i) = oa;
        *reinterpret_cast<float4*>(opb + i) = ob;
    }
}

// ---------------------------------------------------------------------------
extern "C" void kernel_launch(void* const* d_in, const int* in_sizes, int n_in,
                              void* d_out, int out_size)
{
    const float* query = (const float*)d_in[0];
    const float* key   = (const float*)d_in[1];
    const float* value = (const float*)d_in[2];
    const float* Wq    = (const float*)d_in[3];
    const float* bq    = (const float*)d_in[4];
    const float* Wk    = (const float*)d_in[5];
    const float* bk    = (const float*)d_in[6];
    const float* Wv    = (const float*)d_in[7];
    const float* bv    = (const float*)d_in[8];

    const int smem_bytes = 2 * KT * DHEAD * sizeof(float);  // 65536
    cudaFuncSetAttribute(attn_kernel, cudaFuncAttributeMaxDynamicSharedMemorySize, smem_bytes);

    dim3 pgrid(NROWS / 64, 3);
    proj_kernel<<<pgrid, 256>>>(query, key, value, Wq, Wk, Wv, bq, bk, bv);

    dim3 agrid(SEQ / 64, BATCH);
    attn_kernel<<<agrid, 256, smem_bytes>>>((float*)d_out);
}

// round 4
// speedup vs baseline: 2.4343x; 2.4343x over previous
#include <cuda_runtime.h>

#define BATCH 8
#define SEQ   2048
#define DIN   1024
#define DHEAD 128
#define NROWS (BATCH * SEQ)

// Scratch (allocation-free rule: __device__ globals).
// Q and K are stored TRANSPOSED per batch: [b][d][s] (Q also pre-scaled).
__device__ float g_qt[BATCH * DHEAD * SEQ];
__device__ float g_kt[BATCH * DHEAD * SEQ];
__device__ float g_v [NROWS * DHEAD];

// ---------------------------------------------------------------------------
// Projection GEMM: Y[16384,128] = X[16384,1024] @ W[1024,128] + b
// Same mainloop as R2 (~72% FFMA roofline). Epilogue: Q,K stored transposed
// [b][d][s] (Q pre-scaled by 1/sqrt(128)); V stored row-major.
// ---------------------------------------------------------------------------
__global__ __launch_bounds__(256) void proj_kernel(
    const float* __restrict__ Xq, const float* __restrict__ Xk, const float* __restrict__ Xv,
    const float* __restrict__ Wq, const float* __restrict__ Wk, const float* __restrict__ Wv,
    const float* __restrict__ bq, const float* __restrict__ bk, const float* __restrict__ bv)
{
    const float* X;
    const float* W;
    const float* bias;
    if (blockIdx.y == 0)      { X = Xq; W = Wq; bias = bq; }
    else if (blockIdx.y == 1) { X = Xk; W = Wk; bias = bk; }
    else                      { X = Xv; W = Wv; bias = bv; }

    __shared__ float As[16][64];
    __shared__ float Bs[16][128];

    const int row0 = blockIdx.x * 64;
    const int t  = threadIdx.x;
    const int ty = t >> 4;
    const int tx = t & 15;

    float acc[4][8];
#pragma unroll
    for (int i = 0; i < 4; i++)
#pragma unroll
        for (int j = 0; j < 8; j++) acc[i][j] = 0.f;

    const int ar = t >> 2;
    const int ak = (t & 3) << 2;
    const int bn = (t & 31) << 2;
    const int bk0 = t >> 5;

    for (int k0 = 0; k0 < DIN; k0 += 16) {
        float4 a4  = *reinterpret_cast<const float4*>(X + (size_t)(row0 + ar) * DIN + k0 + ak);
        float4 b4a = *reinterpret_cast<const float4*>(W + (size_t)(k0 + bk0) * DHEAD + bn);
        float4 b4b = *reinterpret_cast<const float4*>(W + (size_t)(k0 + 8 + bk0) * DHEAD + bn);

        __syncthreads();
        As[ak + 0][ar] = a4.x;
        As[ak + 1][ar] = a4.y;
        As[ak + 2][ar] = a4.z;
        As[ak + 3][ar] = a4.w;
        *reinterpret_cast<float4*>(&Bs[bk0][bn])     = b4a;
        *reinterpret_cast<float4*>(&Bs[bk0 + 8][bn]) = b4b;
        __syncthreads();

#pragma unroll
        for (int kk = 0; kk < 16; kk++) {
            float4 av  = *reinterpret_cast<const float4*>(&As[kk][ty << 2]);
            float4 bv0 = *reinterpret_cast<const float4*>(&Bs[kk][tx << 3]);
            float4 bv1 = *reinterpret_cast<const float4*>(&Bs[kk][(tx << 3) + 4]);
            float a_[4] = {av.x, av.y, av.z, av.w};
            float b_[8] = {bv0.x, bv0.y, bv0.z, bv0.w, bv1.x, bv1.y, bv1.z, bv1.w};
#pragma unroll
            for (int i = 0; i < 4; i++)
#pragma unroll
                for (int j = 0; j < 8; j++)
                    acc[i][j] += a_[i] * b_[j];
        }
    }

    if (blockIdx.y == 2) {
        // V: row-major [s][d]
#pragma unroll
        for (int i = 0; i < 4; i++) {
            float* yp = g_v + (size_t)(row0 + (ty << 2) + i) * DHEAD + (tx << 3);
#pragma unroll
            for (int j = 0; j < 8; j++)
                yp[j] = acc[i][j] + bias[(tx << 3) + j];
        }
    } else {
        // Q/K: transposed [b][d][s]; Q pre-scaled by 1/sqrt(DHEAD)
        float* Yt = (blockIdx.y == 0) ? g_qt : g_kt;
        const float sc = (blockIdx.y == 0) ? 0.088388347648318447f : 1.0f;
#pragma unroll
        for (int i = 0; i < 4; i++) {
            int r = row0 + (ty << 2) + i;
            int bb = r >> 11;            // / SEQ
            int ss = r & (SEQ - 1);
            float* yp = Yt + ((size_t)bb * DHEAD) * SEQ + ss;
#pragma unroll
            for (int j = 0; j < 8; j++) {
                int d = (tx << 3) + j;
                yp[(size_t)d * SEQ] = (acc[i][j] + bias[d]) * sc;
            }
        }
    }
}

// ---------------------------------------------------------------------------
// Flash attention v3: two register-tiled GEMM passes, no transposes in-kernel,
// no shuffles in hot loops. grid (SEQ/64, BATCH), 256 threads, 2 CTAs/SM.
//   pass1: S[64][32] = Qt tile x Kt tile  (thread: 2q x 4k; per d: LDS.64+LDS.128 -> 8 FFMA)
//   softmax: online m/l in registers (3 shfl per row per 32-key chunk)
//   pass2: O[64][128] += P x V           (thread: 4q x 8d; per k: 3 LDS.128 -> 32 FFMA)
// All smem accesses conflict-free (bank notes inline).
// ---------------------------------------------------------------------------
#define QT  64
#define KTT 32
#define QTS 68    // Qt row stride: bank (4d+2tq)&31 -> 4 distinct, dedup ok
#define KTS 36    // Kt row stride: bank (4d+4tk)&31 -> 8 distinct quads, 1 phase
#define VST 132   // Vs row stride
#define PST 68    // Pt row stride: bank (4k+4tq2)&31 -> dedup x16, 1 phase

__global__ __launch_bounds__(256, 2) void attn_kernel(float* __restrict__ O)
{
    extern __shared__ float sm[];
    float* Qt = sm;                       // [128][QTS]  34.8 KB
    float* Kt = Qt + DHEAD * QTS;         // [128][KTS]  18.4 KB
    float* Vs = Kt + DHEAD * KTS;         // [32][VST]   16.9 KB
    float* Pt = Vs + KTT * VST;           // [32][PST]    8.7 KB
    float* aS = Pt + KTT * PST;           // alpha[64]
    float* lS = aS + QT;                  // l[64]

    const int b  = blockIdx.y;
    const int q0 = blockIdx.x * QT;
    const int t  = threadIdx.x;
    const int tq  = t >> 3;   // pass1: rows 2tq, 2tq+1
    const int tk  = t & 7;    // pass1: cols 4tk..4tk+3
    const int tq2 = t >> 4;   // pass2: rows 4tq2..4tq2+3
    const int td  = t & 15;   // pass2: cols 4td..+3 and 64+4td..+3

    // ---- stage Qt tile [128][64] (pre-transposed & pre-scaled in gmem) ----
    {
        const float* qg = g_qt + (size_t)b * DHEAD * SEQ + q0;
#pragma unroll
        for (int u = 0; u < 8; u++) {
            int f = t + (u << 8);          // f4 id 0..2047
            int d = f >> 4;                // 16 f4 per d-row
            int x = (f & 15) << 2;
            float4 v = *reinterpret_cast<const float4*>(qg + (size_t)d * SEQ + x);
            *reinterpret_cast<float4*>(Qt + d * QTS + x) = v;
        }
    }

    float m0 = -1e30f, m1 = -1e30f, l0 = 0.f, l1 = 0.f;
    float acc[4][8];
#pragma unroll
    for (int i = 0; i < 4; i++)
#pragma unroll
        for (int j = 0; j < 8; j++) acc[i][j] = 0.f;

    const float* ktg = g_kt + (size_t)b * DHEAD * SEQ;
    const float* vg  = g_v  + (size_t)b * SEQ * DHEAD;

    for (int j0 = 0; j0 < SEQ; j0 += KTT) {
        __syncthreads();   // prev pass2 done with Vs/Pt (and Qt staging on iter 0)

        // ---- load K tile [128 d][32 keys] (coalesced 128B rows) ----
#pragma unroll
        for (int u = 0; u < 4; u++) {
            int f = t + (u << 8);          // 0..1023
            int d = f >> 3;                // 8 f4 per d-row
            int x = (f & 7) << 2;
            float4 v = *reinterpret_cast<const float4*>(ktg + (size_t)d * SEQ + j0 + x);
            *reinterpret_cast<float4*>(Kt + d * KTS + x) = v;
        }
        // ---- load V tile [32 rows][128] ----
#pragma unroll
        for (int u = 0; u < 4; u++) {
            int f = t + (u << 8);
            int r = f >> 5;
            int c = (f & 31) << 2;
            *reinterpret_cast<float4*>(Vs + r * VST + c) =
                *reinterpret_cast<const float4*>(vg + (size_t)(j0 + r) * DHEAD + c);
        }
        __syncthreads();

        // ---- pass 1: S = Q K^T (outer product over d) ----
        float s[2][4];
#pragma unroll
        for (int j = 0; j < 4; j++) { s[0][j] = 0.f; s[1][j] = 0.f; }

#pragma unroll 8
        for (int d = 0; d < DHEAD; d++) {
            float2 qv = *reinterpret_cast<const float2*>(Qt + d * QTS + (tq << 1));
            float4 kv = *reinterpret_cast<const float4*>(Kt + d * KTS + (tk << 2));
            s[0][0] += qv.x * kv.x;  s[0][1] += qv.x * kv.y;
            s[0][2] += qv.x * kv.z;  s[0][3] += qv.x * kv.w;
            s[1][0] += qv.y * kv.x;  s[1][1] += qv.y * kv.y;
            s[1][2] += qv.y * kv.z;  s[1][3] += qv.y * kv.w;
        }

        // ---- online softmax for rows 2tq, 2tq+1 (reduce over 8 tk lanes) ----
        float t0 = fmaxf(fmaxf(s[0][0], s[0][1]), fmaxf(s[0][2], s[0][3]));
        float t1 = fmaxf(fmaxf(s[1][0], s[1][1]), fmaxf(s[1][2], s[1][3]));
#pragma unroll
        for (int o = 1; o < 8; o <<= 1) {
            t0 = fmaxf(t0, __shfl_xor_sync(0xffffffffu, t0, o));
            t1 = fmaxf(t1, __shfl_xor_sync(0xffffffffu, t1, o));
        }
        float mn0 = fmaxf(m0, t0), mn1 = fmaxf(m1, t1);
        float a0 = __expf(m0 - mn0), a1 = __expf(m1 - mn1);
        m0 = mn0; m1 = mn1;

        float p0[4], p1[4];
        float ls0 = 0.f, ls1 = 0.f;
#pragma unroll
        for (int j = 0; j < 4; j++) {
            p0[j] = __expf(s[0][j] - mn0);  ls0 += p0[j];
            p1[j] = __expf(s[1][j] - mn1);  ls1 += p1[j];
        }
#pragma unroll
        for (int o = 1; o < 8; o <<= 1) {
            ls0 += __shfl_xor_sync(0xffffffffu, ls0, o);
            ls1 += __shfl_xor_sync(0xffffffffu, ls1, o);
        }
        l0 = l0 * a0 + ls0;
        l1 = l1 * a1 + ls1;

        // write P transposed [k][q]
#pragma unroll
        for (int j = 0; j < 4; j++) {
            Pt[((tk << 2) + j) * PST + (tq << 1)    ] = p0[j];
            Pt[((tk << 2) + j) * PST + (tq << 1) + 1] = p1[j];
        }
        if (tk == 0) {
            aS[(tq << 1)    ] = a0;  aS[(tq << 1) + 1] = a1;
            lS[(tq << 1)    ] = l0;  lS[(tq << 1) + 1] = l1;
        }
        __syncthreads();

        // ---- pass 2: acc = acc*alpha + P V ----
        float al[4];
#pragma unroll
        for (int i = 0; i < 4; i++) al[i] = aS[(tq2 << 2) + i];
#pragma unroll
        for (int i = 0; i < 4; i++)
#pragma unroll
            for (int j = 0; j < 8; j++) acc[i][j] *= al[i];

#pragma unroll 4
        for (int k = 0; k < KTT; k++) {
            float4 pf = *reinterpret_cast<const float4*>(Pt + k * PST + (tq2 << 2));
            float4 v0 = *reinterpret_cast<const float4*>(Vs + k * VST + (td << 2));
            float4 v1 = *reinterpret_cast<const float4*>(Vs + k * VST + 64 + (td << 2));
            acc[0][0] += pf.x * v0.x;  acc[0][1] += pf.x * v0.y;
            acc[0][2] += pf.x * v0.z;  acc[0][3] += pf.x * v0.w;
            acc[0][4] += pf.x * v1.x;  acc[0][5] += pf.x * v1.y;
            acc[0][6] += pf.x * v1.z;  acc[0][7] += pf.x * v1.w;
            acc[1][0] += pf.y * v0.x;  acc[1][1] += pf.y * v0.y;
            acc[1][2] += pf.y * v0.z;  acc[1][3] += pf.y * v0.w;
            acc[1][4] += pf.y * v1.x;  acc[1][5] += pf.y * v1.y;
            acc[1][6] += pf.y * v1.z;  acc[1][7] += pf.y * v1.w;
            acc[2][0] += pf.z * v0.x;  acc[2][1] += pf.z * v0.y;
            acc[2][2] += pf.z * v0.z;  acc[2][3] += pf.z * v0.w;
            acc[2][4] += pf.z * v1.x;  acc[2][5] += pf.z * v1.y;
            acc[2][6] += pf.z * v1.z;  acc[2][7] += pf.z * v1.w;
            acc[3][0] += pf.w * v0.x;  acc[3][1] += pf.w * v0.y;
            acc[3][2] += pf.w * v0.z;  acc[3][3] += pf.w * v0.w;
            acc[3][4] += pf.w * v1.x;  acc[3][5] += pf.w * v1.y;
            acc[3][6] += pf.w * v1.z;  acc[3][7] += pf.w * v1.w;
        }
    }

    // ---- epilogue: normalize and store (lS final after last in-loop sync) ----
#pragma unroll
    for (int i = 0; i < 4; i++) {
        int r = q0 + (tq2 << 2) + i;
        float inv = 1.0f / lS[(tq2 << 2) + i];
        float* op = O + (size_t)(b * SEQ + r) * DHEAD;
        float4 o0 = {acc[i][0] * inv, acc[i][1] * inv, acc[i][2] * inv, acc[i][3] * inv};
        float4 o1 = {acc[i][4] * inv, acc[i][5] * inv, acc[i][6] * inv, acc[i][7] * inv};
        *reinterpret_cast<float4*>(op + (td << 2))      = o0;
        *reinterpret_cast<float4*>(op + 64 + (td << 2)) = o1;
    }
}

// ---------------------------------------------------------------------------
extern "C" void kernel_launch(void* const* d_in, const int* in_sizes, int n_in,
                              void* d_out, int out_size)
{
    const float* query = (const float*)d_in[0];
    const float* key   = (const float*)d_in[1];
    const float* value = (const float*)d_in[2];
    const float* Wq    = (const float*)d_in[3];
    const float* bq    = (const float*)d_in[4];
    const float* Wk    = (const float*)d_in[5];
    const float* bk    = (const float*)d_in[6];
    const float* Wv    = (const float*)d_in[7];
    const float* bv    = (const float*)d_in[8];

    const int smem_bytes = (DHEAD * QTS + DHEAD * KTS + KTT * VST + KTT * PST + 2 * QT)
                           * (int)sizeof(float);   // ~79.4 KB
    cudaFuncSetAttribute(attn_kernel, cudaFuncAttributeMaxDynamicSharedMemorySize, smem_bytes);

    dim3 pgrid(NROWS / 64, 3);
    proj_kernel<<<pgrid, 256>>>(query, key, value, Wq, Wk, Wv, bq, bk, bv);

    dim3 agrid(SEQ / QT, BATCH);
    attn_kernel<<<agrid, 256, smem_bytes>>>((float*)d_out);
}

// round 5
// speedup vs baseline: 7.8663x; 3.2315x over previous
#include <cuda_runtime.h>
#include <cstdint>

#define BATCH 8
#define SEQ   2048
#define DIN   1024
#define DHEAD 128
#define NROWS (BATCH * SEQ)

// ---------------- scratch (allocation-free rule) ----------------
// tf32-converted operands for the attention phase:
__device__ uint32_t g_q [NROWS * DHEAD];        // [b][s][d], pre-scaled by 1/sqrt(128)
__device__ uint32_t g_k [NROWS * DHEAD];        // [b][s][d]
__device__ uint32_t g_vt[BATCH * DHEAD * SEQ];  // [b][d][s]  (transposed)
__device__ uint32_t g_wt[3 * DHEAD * DIN];      // W^T per projection: [p][n][k], tf32

// ---------------- helpers ----------------
__device__ __forceinline__ uint32_t cvt_tf32(float x) {
    uint32_t u; asm("cvt.rna.tf32.f32 %0, %1;" : "=r"(u) : "f"(x)); return u;
}
__device__ __forceinline__ uint32_t sptr(const void* p) {
    return (uint32_t)__cvta_generic_to_shared(p);
}
__device__ __forceinline__ void ldsm_x4(uint32_t& r0, uint32_t& r1, uint32_t& r2, uint32_t& r3,
                                        uint32_t a) {
    asm volatile("ldmatrix.sync.aligned.m8n8.x4.shared.b16 {%0,%1,%2,%3}, [%4];"
                 : "=r"(r0), "=r"(r1), "=r"(r2), "=r"(r3) : "r"(a));
}
__device__ __forceinline__ void ldsm_x2(uint32_t& r0, uint32_t& r1, uint32_t a) {
    asm volatile("ldmatrix.sync.aligned.m8n8.x2.shared.b16 {%0,%1}, [%2];"
                 : "=r"(r0), "=r"(r1) : "r"(a));
}
__device__ __forceinline__ void mma8(float* c, uint32_t a0, uint32_t a1, uint32_t a2, uint32_t a3,
                                     uint32_t b0, uint32_t b1) {
    asm volatile("mma.sync.aligned.m16n8k8.row.col.f32.tf32.tf32.f32 "
                 "{%0,%1,%2,%3}, {%4,%5,%6,%7}, {%8,%9}, {%0,%1,%2,%3};"
                 : "+f"(c[0]), "+f"(c[1]), "+f"(c[2]), "+f"(c[3])
                 : "r"(a0), "r"(a1), "r"(a2), "r"(a3), "r"(b0), "r"(b1));
}

// ---------------------------------------------------------------------------
// W transpose + tf32 convert: g_wt[p][n][k] = tf32(W_p[k][n]). Tiny (512KB).
// ---------------------------------------------------------------------------
__global__ void wt_kernel(const float* __restrict__ Wq, const float* __restrict__ Wk,
                          const float* __restrict__ Wv)
{
    int i = blockIdx.x * blockDim.x + threadIdx.x;
    if (i >= 3 * DHEAD * DIN) return;
    int p = i / (DHEAD * DIN);
    int r = i % (DHEAD * DIN);
    int n = r / DIN, k = r % DIN;
    const float* W = (p == 0) ? Wq : (p == 1) ? Wk : Wv;
    g_wt[i] = cvt_tf32(W[k * DHEAD + n]);
}

// ---------------------------------------------------------------------------
// Projection GEMM (tf32 mma): Y[16384,128] = X[16384,1024] W[1024,128] + b
// CTA 128x128, 8 warps (4m x 2n), warp tile 32x64, BK=32.
// Epilogue: p0 -> g_q tf32 scaled, p1 -> g_k tf32, p2 -> g_vt tf32 transposed.
// ---------------------------------------------------------------------------
__global__ __launch_bounds__(256) void proj_kernel(
    const float* __restrict__ Xq, const float* __restrict__ Xk, const float* __restrict__ Xv,
    const float* __restrict__ bq, const float* __restrict__ bk, const float* __restrict__ bv)
{
    __shared__ uint32_t Xs[128 * 36];   // [row][k], tf32
    __shared__ uint32_t Ws[128 * 36];   // [n][k],  tf32 (from g_wt)

    const int p = blockIdx.y;
    const float* X    = (p == 0) ? Xq : (p == 1) ? Xk : Xv;
    const float* bias = (p == 0) ? bq : (p == 1) ? bk : bv;
    const uint32_t* wt = g_wt + (size_t)p * DHEAD * DIN;

    const int row0 = blockIdx.x * 128;
    const int t    = threadIdx.x;
    const int wid  = t >> 5;
    const int lane = t & 31;
    const int g    = lane >> 2;
    const int t4   = lane & 3;
    const int wm   = (wid >> 1) * 32;   // 4 m-groups
    const int wn   = (wid & 1) * 64;    // 2 n-groups

    float acc[2][8][4];
#pragma unroll
    for (int i = 0; i < 2; i++)
#pragma unroll
        for (int j = 0; j < 8; j++)
#pragma unroll
            for (int q = 0; q < 4; q++) acc[i][j][q] = 0.f;

    const uint32_t xs0 = sptr(Xs);
    const uint32_t ws0 = sptr(Ws);
    const int arow = lane & 15, acol = (lane >> 4) << 2;   // ldmatrix A lane map
    const int brow = lane & 7,  bcol = ((lane >> 3) & 1) << 2;

    for (int k0 = 0; k0 < DIN; k0 += 32) {
        __syncthreads();
#pragma unroll
        for (int u = 0; u < 4; u++) {
            int f = t + (u << 8);
            int r = f >> 3, c = (f & 7) << 2;
            float4 v = *reinterpret_cast<const float4*>(X + (size_t)(row0 + r) * DIN + k0 + c);
            uint32_t* d = Xs + r * 36 + c;
            d[0] = cvt_tf32(v.x); d[1] = cvt_tf32(v.y);
            d[2] = cvt_tf32(v.z); d[3] = cvt_tf32(v.w);
        }
#pragma unroll
        for (int u = 0; u < 4; u++) {
            int f = t + (u << 8);
            int r = f >> 3, c = (f & 7) << 2;
            *reinterpret_cast<uint4*>(Ws + r * 36 + c) =
                *reinterpret_cast<const uint4*>(wt + (size_t)r * DIN + k0 + c);
        }
        __syncthreads();

#pragma unroll
        for (int kk = 0; kk < 4; kk++) {
            uint32_t a[2][4];
#pragma unroll
            for (int mi = 0; mi < 2; mi++)
                ldsm_x4(a[mi][0], a[mi][1], a[mi][2], a[mi][3],
                        xs0 + ((wm + mi * 16 + arow) * 36 + kk * 8 + acol) * 4);
#pragma unroll
            for (int nt = 0; nt < 8; nt++) {
                uint32_t b0, b1;
                ldsm_x2(b0, b1, ws0 + ((wn + nt * 8 + brow) * 36 + kk * 8 + bcol) * 4);
                mma8(acc[0][nt], a[0][0], a[0][1], a[0][2], a[0][3], b0, b1);
                mma8(acc[1][nt], a[1][0], a[1][1], a[1][2], a[1][3], b0, b1);
            }
        }
    }

    const float sc = (p == 0) ? 0.088388347648318447f : 1.0f;
#pragma unroll
    for (int mi = 0; mi < 2; mi++) {
#pragma unroll
        for (int nt = 0; nt < 8; nt++) {
            int col = wn + nt * 8 + (t4 << 1);
#pragma unroll
            for (int half = 0; half < 2; half++) {
                int row = row0 + wm + mi * 16 + g + half * 8;
                float v0 = (acc[mi][nt][half * 2 + 0] + bias[col])     * sc;
                float v1 = (acc[mi][nt][half * 2 + 1] + bias[col + 1]) * sc;
                if (p == 2) {
                    int bb = row >> 11, ss = row & (SEQ - 1);
                    g_vt[(size_t)bb * DHEAD * SEQ + (size_t)col       * SEQ + ss] = cvt_tf32(v0);
                    g_vt[(size_t)bb * DHEAD * SEQ + (size_t)(col + 1) * SEQ + ss] = cvt_tf32(v1);
                } else {
                    uint32_t* out = (p == 0) ? g_q : g_k;
                    out[(size_t)row * DHEAD + col]     = cvt_tf32(v0);
                    out[(size_t)row * DHEAD + col + 1] = cvt_tf32(v1);
                }
            }
        }
    }
}

// ---------------------------------------------------------------------------
// Flash attention (tf32 mma): grid (SEQ/64, BATCH), 256 thr, 2 CTAs/SM.
// Per 32-key tile:  pass1 S=Q K^T (warp 16q x 16k, mma),
//                   softmax in smem (online m/l, quad shuffles),
//                   pass2 O += P V  (warp 32q x 32d, mma, V d-major).
// ---------------------------------------------------------------------------
#define QST 132   // Qs/Ks row stride (mod 32 = 4 -> conflict-free ldmatrix)
#define VST 36    // Vt/SP row stride

__global__ __launch_bounds__(256, 2) void attn_kernel(float* __restrict__ O)
{
    extern __shared__ uint32_t sm4[];
    uint32_t* Qs = sm4;                  // [64][132] tf32
    uint32_t* Ks = Qs + 64 * QST;        // [32][132] tf32
    uint32_t* Vt = Ks + 32 * QST;        // [128][36] tf32 (d-major)
    uint32_t* SP = Vt + 128 * VST;       // [64][36]  f32 scores -> tf32 P in place
    float* mS = (float*)(SP + 64 * VST);
    float* lS = mS + 64;
    float* aS = lS + 64;

    const int b    = blockIdx.y;
    const int q0   = blockIdx.x * 64;
    const int t    = threadIdx.x;
    const int wid  = t >> 5;
    const int lane = t & 31;
    const int g    = lane >> 2;
    const int t4   = lane & 3;

    const int wm1 = (wid >> 1) * 16, wn1 = (wid & 1) * 16;   // pass1: 4m x 2n
    const int wm2 = (wid & 1) * 32,  wn2 = (wid >> 1) * 32;  // pass2: 2m x 4n
    const int srow = t >> 2, sc0 = (t & 3) * 8;              // softmax ownership

    const uint32_t qs0 = sptr(Qs), ks0 = sptr(Ks);
    const uint32_t vt0 = sptr(Vt), sp0 = sptr(SP);
    const int arow = lane & 15, acol = (lane >> 4) << 2;
    const int brow = lane & 7,  bcol = ((lane >> 3) & 1) << 2;

    // stage Q tile (tf32 pre-scaled in gmem)
    {
        const uint32_t* qg = g_q + (size_t)(b * SEQ + q0) * DHEAD;
#pragma unroll
        for (int u = 0; u < 8; u++) {
            int f = t + (u << 8);
            int r = f >> 5, c = (f & 31) << 2;
            *reinterpret_cast<uint4*>(Qs + r * QST + c) =
                *reinterpret_cast<const uint4*>(qg + (size_t)r * DHEAD + c);
        }
    }
    if (t < 64) { mS[t] = -1e30f; lS[t] = 0.f; }

    float acc[2][4][4];
#pragma unroll
    for (int i = 0; i < 2; i++)
#pragma unroll
        for (int j = 0; j < 4; j++)
#pragma unroll
            for (int q = 0; q < 4; q++) acc[i][j][q] = 0.f;

    const uint32_t* kg = g_k  + (size_t)b * SEQ * DHEAD;
    const uint32_t* vg = g_vt + (size_t)b * DHEAD * SEQ;

    for (int j0 = 0; j0 < SEQ; j0 += 32) {
        __syncthreads();
        // K tile [32 keys][128 d]
#pragma unroll
        for (int u = 0; u < 4; u++) {
            int f = t + (u << 8);
            int r = f >> 5, c = (f & 31) << 2;
            *reinterpret_cast<uint4*>(Ks + r * QST + c) =
                *reinterpret_cast<const uint4*>(kg + (size_t)(j0 + r) * DHEAD + c);
        }
        // V tile [128 d][32 keys] (gmem already d-major)
#pragma unroll
        for (int u = 0; u < 4; u++) {
            int f = t + (u << 8);
            int r = f >> 3, c = (f & 7) << 2;
            *reinterpret_cast<uint4*>(Vt + r * VST + c) =
                *reinterpret_cast<const uint4*>(vg + (size_t)r * SEQ + j0 + c);
        }
        __syncthreads();

        // ---- pass 1: S[16q x 16k] per warp ----
        float s[2][4];
#pragma unroll
        for (int j = 0; j < 2; j++)
#pragma unroll
            for (int q = 0; q < 4; q++) s[j][q] = 0.f;

#pragma unroll
        for (int kk = 0; kk < 16; kk++) {
            uint32_t a0, a1, a2, a3;
            ldsm_x4(a0, a1, a2, a3, qs0 + ((wm1 + arow) * QST + kk * 8 + acol) * 4);
#pragma unroll
            for (int nt = 0; nt < 2; nt++) {
                uint32_t b0, b1;
                ldsm_x2(b0, b1, ks0 + ((wn1 + nt * 8 + brow) * QST + kk * 8 + bcol) * 4);
                mma8(s[nt], a0, a1, a2, a3, b0, b1);
            }
        }
        // store S to smem (fp32)
#pragma unroll
        for (int nt = 0; nt < 2; nt++) {
            float* r0 = (float*)SP + (wm1 + g) * VST + wn1 + nt * 8 + (t4 << 1);
            r0[0] = s[nt][0];  r0[1] = s[nt][1];
            float* r1 = r0 + 8 * VST;
            r1[0] = s[nt][2];  r1[1] = s[nt][3];
        }
        __syncthreads();

        // ---- softmax: thread owns row srow, cols sc0..sc0+7 ----
        {
            float* Sf = (float*)SP + srow * VST + sc0;
            float v[8];
#pragma unroll
            for (int j = 0; j < 8; j++) v[j] = Sf[j];
            float tmax = v[0];
#pragma unroll
            for (int j = 1; j < 8; j++) tmax = fmaxf(tmax, v[j]);
            tmax = fmaxf(tmax, __shfl_xor_sync(0xffffffffu, tmax, 1));
            tmax = fmaxf(tmax, __shfl_xor_sync(0xffffffffu, tmax, 2));
            float mold = mS[srow];
            float mnew = fmaxf(mold, tmax);
            float alpha = __expf(mold - mnew);
            float lsum = 0.f;
            uint32_t* Pu = SP + srow * VST + sc0;
#pragma unroll
            for (int j = 0; j < 8; j++) {
                float pj = __expf(v[j] - mnew);
                lsum += pj;
                Pu[j] = cvt_tf32(pj);
            }
            lsum += __shfl_xor_sync(0xffffffffu, lsum, 1);
            lsum += __shfl_xor_sync(0xffffffffu, lsum, 2);
            if ((t & 3) == 0) {
                mS[srow] = mnew;
                lS[srow] = lS[srow] * alpha + lsum;
                aS[srow] = alpha;
            }
        }
        __syncthreads();

        // ---- pass 2: O[32q x 32d] per warp,  acc = acc*alpha + P V ----
#pragma unroll
        for (int mi = 0; mi < 2; mi++) {
            float a0 = aS[wm2 + mi * 16 + g];
            float a1 = aS[wm2 + mi * 16 + g + 8];
#pragma unroll
            for (int nt = 0; nt < 4; nt++) {
                acc[mi][nt][0] *= a0;  acc[mi][nt][1] *= a0;
                acc[mi][nt][2] *= a1;  acc[mi][nt][3] *= a1;
            }
        }
#pragma unroll
        for (int kk = 0; kk < 4; kk++) {
            uint32_t a[2][4];
#pragma unroll
            for (int mi = 0; mi < 2; mi++)
                ldsm_x4(a[mi][0], a[mi][1], a[mi][2], a[mi][3],
                        sp0 + ((wm2 + mi * 16 + arow) * VST + kk * 8 + acol) * 4);
#pragma unroll
            for (int nt = 0; nt < 4; nt++) {
                uint32_t b0, b1;
                ldsm_x2(b0, b1, vt0 + ((wn2 + nt * 8 + brow) * VST + kk * 8 + bcol) * 4);
                mma8(acc[0][nt], a[0][0], a[0][1], a[0][2], a[0][3], b0, b1);
                mma8(acc[1][nt], a[1][0], a[1][1], a[1][2], a[1][3], b0, b1);
            }
        }
    }

    // ---- epilogue: O = acc / l ----
#pragma unroll
    for (int mi = 0; mi < 2; mi++) {
        int r0 = wm2 + mi * 16 + g;
        float inv0 = 1.0f / lS[r0];
        float inv1 = 1.0f / lS[r0 + 8];
#pragma unroll
        for (int nt = 0; nt < 4; nt++) {
            int col = wn2 + nt * 8 + (t4 << 1);
            float2 o0 = {acc[mi][nt][0] * inv0, acc[mi][nt][1] * inv0};
            float2 o1 = {acc[mi][nt][2] * inv1, acc[mi][nt][3] * inv1};
            *reinterpret_cast<float2*>(O + (size_t)(b * SEQ + q0 + r0)     * DHEAD + col) = o0;
            *reinterpret_cast<float2*>(O + (size_t)(b * SEQ + q0 + r0 + 8) * DHEAD + col) = o1;
        }
    }
}

// ---------------------------------------------------------------------------
extern "C" void kernel_launch(void* const* d_in, const int* in_sizes, int n_in,
                              void* d_out, int out_size)
{
    const float* query = (const float*)d_in[0];
    const float* key   = (const float*)d_in[1];
    const float* value = (const float*)d_in[2];
    const float* Wq    = (const float*)d_in[3];
    const float* bq    = (const float*)d_in[4];
    const float* Wk    = (const float*)d_in[5];
    const float* bk    = (const float*)d_in[6];
    const float* Wv    = (const float*)d_in[7];
    const float* bv    = (const float*)d_in[8];

    const int attn_smem = (64 * QST + 32 * QST + 128 * VST + 64 * VST) * 4 + 3 * 64 * 4; // 79104
    cudaFuncSetAttribute(attn_kernel, cudaFuncAttributeMaxDynamicSharedMemorySize, attn_smem);

    wt_kernel<<<(3 * DHEAD * DIN + 255) / 256, 256>>>(Wq, Wk, Wv);

    dim3 pgrid(NROWS / 128, 3);
    proj_kernel<<<pgrid, 256>>>(query, key, value, bq, bk, bv);

    dim3 agrid(SEQ / 64, BATCH);
    attn_kernel<<<agrid, 256, attn_smem>>>((float*)d_out);
}

// round 7
// speedup vs baseline: 9.7583x; 1.2405x over previous
#include <cuda_runtime.h>
#include <cstdint>

#define BATCH 8
#define SEQ   2048
#define DIN   1024
#define DHEAD 128
#define NROWS (BATCH * SEQ)

// ---------------- scratch (allocation-free rule) ----------------
__device__ uint32_t g_q [NROWS * DHEAD];        // [b][s][d], tf32, pre-scaled
__device__ uint32_t g_k [NROWS * DHEAD];        // [b][s][d], tf32
__device__ uint32_t g_vt[BATCH * DHEAD * SEQ];  // [b][d][s], tf32 (transposed)
__device__ uint32_t g_wt[3 * DHEAD * DIN];      // W^T per projection: [p][n][k], tf32

// ---------------- helpers ----------------
__device__ __forceinline__ uint32_t cvt_tf32(float x) {
    uint32_t u; asm("cvt.rna.tf32.f32 %0, %1;" : "=r"(u) : "f"(x)); return u;
}
__device__ __forceinline__ uint32_t sptr(const void* p) {
    return (uint32_t)__cvta_generic_to_shared(p);
}
__device__ __forceinline__ void ldsm_x4(uint32_t& r0, uint32_t& r1, uint32_t& r2, uint32_t& r3,
                                        uint32_t a) {
    asm volatile("ldmatrix.sync.aligned.m8n8.x4.shared.b16 {%0,%1,%2,%3}, [%4];"
                 : "=r"(r0), "=r"(r1), "=r"(r2), "=r"(r3) : "r"(a));
}
__device__ __forceinline__ void ldsm_x2(uint32_t& r0, uint32_t& r1, uint32_t a) {
    asm volatile("ldmatrix.sync.aligned.m8n8.x2.shared.b16 {%0,%1}, [%2];"
                 : "=r"(r0), "=r"(r1) : "r"(a));
}
__device__ __forceinline__ void mma8(float* c, uint32_t a0, uint32_t a1, uint32_t a2, uint32_t a3,
                                     uint32_t b0, uint32_t b1) {
    asm volatile("mma.sync.aligned.m16n8k8.row.col.f32.tf32.tf32.f32 "
                 "{%0,%1,%2,%3}, {%4,%5,%6,%7}, {%8,%9}, {%0,%1,%2,%3};"
                 : "+f"(c[0]), "+f"(c[1]), "+f"(c[2]), "+f"(c[3])
                 : "r"(a0), "r"(a1), "r"(a2), "r"(a3), "r"(b0), "r"(b1));
}
__device__ __forceinline__ void cp16(uint32_t s, const void* g) {
    asm volatile("cp.async.cg.shared.global [%0], [%1], 16;" :: "r"(s), "l"(g));
}
__device__ __forceinline__ void cp_commit() {
    asm volatile("cp.async.commit_group;");
}
template <int N>
__device__ __forceinline__ void cp_wait() {
    asm volatile("cp.async.wait_group %0;" :: "n"(N));
}

// ---------------------------------------------------------------------------
// W transpose + tf32 convert: g_wt[p][n][k] = tf32(W_p[k][n]).
// ---------------------------------------------------------------------------
__global__ void wt_kernel(const float* __restrict__ Wq, const float* __restrict__ Wk,
                          const float* __restrict__ Wv)
{
    int i = blockIdx.x * blockDim.x + threadIdx.x;
    if (i >= 3 * DHEAD * DIN) return;
    int p = i / (DHEAD * DIN);
    int r = i % (DHEAD * DIN);
    int n = r / DIN, k = r % DIN;
    const float* W = (p == 0) ? Wq : (p == 1) ? Wk : Wv;
    g_wt[i] = cvt_tf32(W[k * DHEAD + n]);
}

// ---------------------------------------------------------------------------
// Projection GEMM (tf32 mma, double-buffered): Y = X W + b
// CTA 128x128, 8 warps (4m x 2n), BK=32. X prefetched via regs (needs cvt),
// W prefetched via cp.async (already tf32 in gmem). One sync per k-step.
// FIX vs R6: full-tile loads restored (4 chunks/thread, 128 rows covered).
// ---------------------------------------------------------------------------
#define PBUF 4608   // 128*36 words per buffer

__global__ __launch_bounds__(256, 2) void proj_kernel(
    const float* __restrict__ Xq, const float* __restrict__ Xk, const float* __restrict__ Xv,
    const float* __restrict__ bq, const float* __restrict__ bk, const float* __restrict__ bv)
{
    extern __shared__ uint32_t psm[];
    uint32_t* Xs = psm;             // [2][128][36] tf32
    uint32_t* Ws = psm + 2 * PBUF;  // [2][128][36] tf32

    const int p = blockIdx.y;
    const float* X    = (p == 0) ? Xq : (p == 1) ? Xk : Xv;
    const float* bias = (p == 0) ? bq : (p == 1) ? bk : bv;
    const uint32_t* wt = g_wt + (size_t)p * DHEAD * DIN;

    const int row0 = blockIdx.x * 128;
    const int t    = threadIdx.x;
    const int wid  = t >> 5;
    const int lane = t & 31;
    const int g    = lane >> 2;
    const int t4   = lane & 3;
    const int wm   = (wid >> 1) * 32;
    const int wn   = (wid & 1) * 64;

    float acc[2][8][4];
#pragma unroll
    for (int i = 0; i < 2; i++)
#pragma unroll
        for (int j = 0; j < 8; j++)
#pragma unroll
            for (int q = 0; q < 4; q++) acc[i][j][q] = 0.f;

    const uint32_t xsb = sptr(Xs);
    const uint32_t wsb = sptr(Ws);
    const int arow = lane & 15, acol = (lane >> 4) << 2;
    const int brow = lane & 7,  bcol = ((lane >> 3) & 1) << 2;

    float4 xv[4];

    // ---- preamble: stage k0=0 into buffer 0 (full 128x32 tiles) ----
#pragma unroll
    for (int u = 0; u < 4; u++) {
        int f = t + (u << 8);
        int r = f >> 3, c = (f & 7) << 2;
        xv[u] = *reinterpret_cast<const float4*>(X + (size_t)(row0 + r) * DIN + c);
        cp16(wsb + (r * 36 + c) * 4, wt + (size_t)r * DIN + c);
    }
    cp_commit();
#pragma unroll
    for (int u = 0; u < 4; u++) {
        int f = t + (u << 8);
        int r = f >> 3, c = (f & 7) << 2;
        uint32_t* d = Xs + r * 36 + c;
        d[0] = cvt_tf32(xv[u].x); d[1] = cvt_tf32(xv[u].y);
        d[2] = cvt_tf32(xv[u].z); d[3] = cvt_tf32(xv[u].w);
    }
    cp_wait<0>();
    __syncthreads();

    for (int k0 = 0; k0 < DIN; k0 += 32) {
        const int cur = (k0 >> 5) & 1;
        const int nxt = cur ^ 1;
        const bool has_next = (k0 + 32) < DIN;

        // prefetch next k-step (full tiles)
        if (has_next) {
#pragma unroll
            for (int u = 0; u < 4; u++) {
                int f = t + (u << 8);
                int r = f >> 3, c = (f & 7) << 2;
                xv[u] = *reinterpret_cast<const float4*>(
                    X + (size_t)(row0 + r) * DIN + k0 + 32 + c);
                cp16(wsb + (nxt * PBUF + r * 36 + c) * 4,
                     wt + (size_t)r * DIN + k0 + 32 + c);
            }
            cp_commit();
        }

        // compute from current buffer
        const uint32_t xs0 = xsb + cur * PBUF * 4;
        const uint32_t ws0 = wsb + cur * PBUF * 4;
#pragma unroll
        for (int kk = 0; kk < 4; kk++) {
            uint32_t a[2][4];
#pragma unroll
            for (int mi = 0; mi < 2; mi++)
                ldsm_x4(a[mi][0], a[mi][1], a[mi][2], a[mi][3],
                        xs0 + ((wm + mi * 16 + arow) * 36 + kk * 8 + acol) * 4);
#pragma unroll
            for (int nt = 0; nt < 8; nt++) {
                uint32_t b0, b1;
                ldsm_x2(b0, b1, ws0 + ((wn + nt * 8 + brow) * 36 + kk * 8 + bcol) * 4);
                mma8(acc[0][nt], a[0][0], a[0][1], a[0][2], a[0][3], b0, b1);
                mma8(acc[1][nt], a[1][0], a[1][1], a[1][2], a[1][3], b0, b1);
            }
        }

        if (has_next) {
#pragma unroll
            for (int u = 0; u < 4; u++) {
                int f = t + (u << 8);
                int r = f >> 3, c = (f & 7) << 2;
                uint32_t* d = Xs + nxt * PBUF + r * 36 + c;
                d[0] = cvt_tf32(xv[u].x); d[1] = cvt_tf32(xv[u].y);
                d[2] = cvt_tf32(xv[u].z); d[3] = cvt_tf32(xv[u].w);
            }
        }
        cp_wait<0>();
        __syncthreads();
    }

    const float sc = (p == 0) ? 0.088388347648318447f : 1.0f;
#pragma unroll
    for (int mi = 0; mi < 2; mi++) {
#pragma unroll
        for (int nt = 0; nt < 8; nt++) {
            int col = wn + nt * 8 + (t4 << 1);
#pragma unroll
            for (int half = 0; half < 2; half++) {
                int row = row0 + wm + mi * 16 + g + half * 8;
                float v0 = (acc[mi][nt][half * 2 + 0] + bias[col])     * sc;
                float v1 = (acc[mi][nt][half * 2 + 1] + bias[col + 1]) * sc;
                if (p == 2) {
                    int bb = row >> 11, ss = row & (SEQ - 1);
                    g_vt[(size_t)bb * DHEAD * SEQ + (size_t)col       * SEQ + ss] = cvt_tf32(v0);
                    g_vt[(size_t)bb * DHEAD * SEQ + (size_t)(col + 1) * SEQ + ss] = cvt_tf32(v1);
                } else {
                    uint32_t* out = (p == 0) ? g_q : g_k;
                    out[(size_t)row * DHEAD + col]     = cvt_tf32(v0);
                    out[(size_t)row * DHEAD + col + 1] = cvt_tf32(v1);
                }
            }
        }
    }
}

// ---------------------------------------------------------------------------
// Flash attention (tf32 mma + cp.async pipelining): grid (SEQ/64, BATCH),
// 256 thr, 2 CTAs/SM. K tile double-buffered (K(i+1) lands during iter i);
// V single-buffered (issued at iter top, needed only by pass2).
// ---------------------------------------------------------------------------
#define QST 132   // Qs/Ks row stride (mod 32 = 4 -> conflict-free ldmatrix)
#define VST 36    // Vt/SP row stride
#define KBUF (32 * QST)

__global__ __launch_bounds__(256, 2) void attn_kernel(float* __restrict__ O)
{
    extern __shared__ uint32_t sm4[];
    uint32_t* Qs = sm4;                  // [64][132] tf32
    uint32_t* Ks = Qs + 64 * QST;        // [2][32][132] tf32
    uint32_t* Vt = Ks + 2 * KBUF;        // [128][36] tf32 (d-major)
    uint32_t* SP = Vt + 128 * VST;       // [64][36]  f32 scores -> tf32 P in place
    float* mS = (float*)(SP + 64 * VST);
    float* lS = mS + 64;
    float* aS = lS + 64;

    const int b    = blockIdx.y;
    const int q0   = blockIdx.x * 64;
    const int t    = threadIdx.x;
    const int wid  = t >> 5;
    const int lane = t & 31;
    const int g    = lane >> 2;
    const int t4   = lane & 3;

    const int wm1 = (wid >> 1) * 16, wn1 = (wid & 1) * 16;   // pass1: 4m x 2n
    const int wm2 = (wid & 1) * 32,  wn2 = (wid >> 1) * 32;  // pass2: 2m x 4n
    const int srow = t >> 2, sc0 = (t & 3) * 8;

    const uint32_t qs0 = sptr(Qs), ksb = sptr(Ks);
    const uint32_t vt0 = sptr(Vt), sp0 = sptr(SP);
    const int arow = lane & 15, acol = (lane >> 4) << 2;
    const int brow = lane & 7,  bcol = ((lane >> 3) & 1) << 2;

    const uint32_t* kg = g_k  + (size_t)b * SEQ * DHEAD;
    const uint32_t* vg = g_vt + (size_t)b * DHEAD * SEQ;

    // stage Q tile
    {
        const uint32_t* qg = g_q + (size_t)(b * SEQ + q0) * DHEAD;
#pragma unroll
        for (int u = 0; u < 8; u++) {
            int f = t + (u << 8);
            int r = f >> 5, c = (f & 31) << 2;
            *reinterpret_cast<uint4*>(Qs + r * QST + c) =
                *reinterpret_cast<const uint4*>(qg + (size_t)r * DHEAD + c);
        }
    }
    if (t < 64) { mS[t] = -1e30f; lS[t] = 0.f; }

    // preamble: async-load K tile 0 into Ks buffer 0
#pragma unroll
    for (int u = 0; u < 4; u++) {
        int f = t + (u << 8);
        int r = f >> 5, c = (f & 31) << 2;
        cp16(ksb + (r * QST + c) * 4, kg + (size_t)r * DHEAD + c);
    }
    cp_commit();

    float acc[2][4][4];
#pragma unroll
    for (int i = 0; i < 2; i++)
#pragma unroll
        for (int j = 0; j < 4; j++)
#pragma unroll
            for (int q = 0; q < 4; q++) acc[i][j][q] = 0.f;

    for (int it = 0; it < SEQ / 32; it++) {
        const int j0 = it * 32;
        const bool hn = (it + 1) < SEQ / 32;
        const uint32_t ks0 = ksb + (it & 1) * KBUF * 4;

        __syncthreads();   // prev pass2 done with Vt/SP; Ks[nxt] free since prev pass1

        // V(it) -> Vt ; K(it+1) -> Ks[nxt]   (async)
#pragma unroll
        for (int u = 0; u < 4; u++) {
            int f = t + (u << 8);
            int rv = f >> 3, cv = (f & 7) << 2;
            cp16(vt0 + (rv * VST + cv) * 4, vg + (size_t)rv * SEQ + j0 + cv);
        }
        cp_commit();
        if (hn) {
#pragma unroll
            for (int u = 0; u < 4; u++) {
                int f = t + (u << 8);
                int r = f >> 5, c = (f & 31) << 2;
                cp16(ksb + ((1 - (it & 1)) * KBUF + r * QST + c) * 4,
                     kg + (size_t)(j0 + 32 + r) * DHEAD + c);
            }
            cp_commit();
        }

        // K(it) resident? (issued a full iteration ago)
        if (hn) cp_wait<2>(); else cp_wait<1>();
        __syncthreads();

        // ---- pass 1: S[16q x 16k] per warp ----
        float s[2][4];
#pragma unroll
        for (int j = 0; j < 2; j++)
#pragma unroll
            for (int q = 0; q < 4; q++) s[j][q] = 0.f;

#pragma unroll
        for (int kk = 0; kk < 16; kk++) {
            uint32_t a0, a1, a2, a3;
            ldsm_x4(a0, a1, a2, a3, qs0 + ((wm1 + arow) * QST + kk * 8 + acol) * 4);
#pragma unroll
            for (int nt = 0; nt < 2; nt++) {
                uint32_t b0, b1;
                ldsm_x2(b0, b1, ks0 + ((wn1 + nt * 8 + brow) * QST + kk * 8 + bcol) * 4);
                mma8(s[nt], a0, a1, a2, a3, b0, b1);
            }
        }
#pragma unroll
        for (int nt = 0; nt < 2; nt++) {
            float* r0 = (float*)SP + (wm1 + g) * VST + wn1 + nt * 8 + (t4 << 1);
            r0[0] = s[nt][0];  r0[1] = s[nt][1];
            float* r1 = r0 + 8 * VST;
            r1[0] = s[nt][2];  r1[1] = s[nt][3];
        }
        // V(it) resident? (had pass1 to land)
        if (hn) cp_wait<1>(); else cp_wait<0>();
        __syncthreads();

        // ---- softmax: thread owns row srow, cols sc0..sc0+7 ----
        {
            float* Sf = (float*)SP + srow * VST + sc0;
            float v[8];
#pragma unroll
            for (int j = 0; j < 8; j++) v[j] = Sf[j];
            float tmax = v[0];
#pragma unroll
            for (int j = 1; j < 8; j++) tmax = fmaxf(tmax, v[j]);
            tmax = fmaxf(tmax, __shfl_xor_sync(0xffffffffu, tmax, 1));
            tmax = fmaxf(tmax, __shfl_xor_sync(0xffffffffu, tmax, 2));
            float mold = mS[srow];
            float mnew = fmaxf(mold, tmax);
            float alpha = __expf(mold - mnew);
            float lsum = 0.f;
            uint32_t* Pu = SP + srow * VST + sc0;
#pragma unroll
            for (int j = 0; j < 8; j++) {
                float pj = __expf(v[j] - mnew);
                lsum += pj;
                Pu[j] = cvt_tf32(pj);
            }
            lsum += __shfl_xor_sync(0xffffffffu, lsum, 1);
            lsum += __shfl_xor_sync(0xffffffffu, lsum, 2);
            if ((t & 3) == 0) {
                mS[srow] = mnew;
                lS[srow] = lS[srow] * alpha + lsum;
                aS[srow] = alpha;
            }
        }
        __syncthreads();

        // ---- pass 2: O[32q x 32d] per warp ----
#pragma unroll
        for (int mi = 0; mi < 2; mi++) {
            float a0 = aS[wm2 + mi * 16 + g];
            float a1 = aS[wm2 + mi * 16 + g + 8];
#pragma unroll
            for (int nt = 0; nt < 4; nt++) {
                acc[mi][nt][0] *= a0;  acc[mi][nt][1] *= a0;
                acc[mi][nt][2] *= a1;  acc[mi][nt][3] *= a1;
            }
        }
#pragma unroll
        for (int kk = 0; kk < 4; kk++) {
            uint32_t a[2][4];
#pragma unroll
            for (int mi = 0; mi < 2; mi++)
                ldsm_x4(a[mi][0], a[mi][1], a[mi][2], a[mi][3],
                        sp0 + ((wm2 + mi * 16 + arow) * VST + kk * 8 + acol) * 4);
#pragma unroll
            for (int nt = 0; nt < 4; nt++) {
                uint32_t b0, b1;
                ldsm_x2(b0, b1, vt0 + ((wn2 + nt * 8 + brow) * VST + kk * 8 + bcol) * 4);
                mma8(acc[0][nt], a[0][0], a[0][1], a[0][2], a[0][3], b0, b1);
                mma8(acc[1][nt], a[1][0], a[1][1], a[1][2], a[1][3], b0, b1);
            }
        }
    }

    // ---- epilogue ----
#pragma unroll
    for (int mi = 0; mi < 2; mi++) {
        int r0 = wm2 + mi * 16 + g;
        float inv0 = 1.0f / lS[r0];
        float inv1 = 1.0f / lS[r0 + 8];
#pragma unroll
        for (int nt = 0; nt < 4; nt++) {
            int col = wn2 + nt * 8 + (t4 << 1);
            float2 o0 = {acc[mi][nt][0] * inv0, acc[mi][nt][1] * inv0};
            float2 o1 = {acc[mi][nt][2] * inv1, acc[mi][nt][3] * inv1};
            *reinterpret_cast<float2*>(O + (size_t)(b * SEQ + q0 + r0)     * DHEAD + col) = o0;
            *reinterpret_cast<float2*>(O + (size_t)(b * SEQ + q0 + r0 + 8) * DHEAD + col) = o1;
        }
    }
}

// ---------------------------------------------------------------------------
extern "C" void kernel_launch(void* const* d_in, const int* in_sizes, int n_in,
                              void* d_out, int out_size)
{
    const float* query = (const float*)d_in[0];
    const float* key   = (const float*)d_in[1];
    const float* value = (const float*)d_in[2];
    const float* Wq    = (const float*)d_in[3];
    const float* bq    = (const float*)d_in[4];
    const float* Wk    = (const float*)d_in[5];
    const float* bk    = (const float*)d_in[6];
    const float* Wv    = (const float*)d_in[7];
    const float* bv    = (const float*)d_in[8];

    const int proj_smem = 4 * PBUF * 4;  // 73728
    cudaFuncSetAttribute(proj_kernel, cudaFuncAttributeMaxDynamicSharedMemorySize, proj_smem);

    const int attn_smem = (64 * QST + 2 * KBUF + 128 * VST + 64 * VST) * 4 + 3 * 64 * 4; // 96000
    cudaFuncSetAttribute(attn_kernel, cudaFuncAttributeMaxDynamicSharedMemorySize, attn_smem);

    wt_kernel<<<(3 * DHEAD * DIN + 255) / 256, 256>>>(Wq, Wk, Wv);

    dim3 pgrid(NROWS / 128, 3);
    proj_kernel<<<pgrid, 256, proj_smem>>>(query, key, value, bq, bk, bv);

    dim3 agrid(SEQ / 64, BATCH);
    attn_kernel<<<agrid, 256, attn_smem>>>((float*)d_out);
}

// round 8
// speedup vs baseline: 11.1077x; 1.1383x over previous
#include <cuda_runtime.h>
#include <cstdint>

#define BATCH 8
#define SEQ   2048
#define DIN   1024
#define DHEAD 128
#define NROWS (BATCH * SEQ)

// ---------------- scratch (allocation-free rule) ----------------
__device__ uint32_t g_q [NROWS * DHEAD];        // [b][s][d], tf32, pre-scaled
__device__ uint32_t g_k [NROWS * DHEAD];        // [b][s][d], tf32
__device__ uint32_t g_vt[BATCH * DHEAD * SEQ];  // [b][d][s], tf32 (transposed)
__device__ uint32_t g_wt[3 * DHEAD * DIN];      // W^T per projection: [p][n][k], tf32

// ---------------- helpers ----------------
__device__ __forceinline__ uint32_t cvt_tf32(float x) {
    uint32_t u; asm("cvt.rna.tf32.f32 %0, %1;" : "=r"(u) : "f"(x)); return u;
}
__device__ __forceinline__ uint32_t sptr(const void* p) {
    return (uint32_t)__cvta_generic_to_shared(p);
}
__device__ __forceinline__ void ldsm_x4(uint32_t& r0, uint32_t& r1, uint32_t& r2, uint32_t& r3,
                                        uint32_t a) {
    asm volatile("ldmatrix.sync.aligned.m8n8.x4.shared.b16 {%0,%1,%2,%3}, [%4];"
                 : "=r"(r0), "=r"(r1), "=r"(r2), "=r"(r3) : "r"(a));
}
__device__ __forceinline__ void ldsm_x2(uint32_t& r0, uint32_t& r1, uint32_t a) {
    asm volatile("ldmatrix.sync.aligned.m8n8.x2.shared.b16 {%0,%1}, [%2];"
                 : "=r"(r0), "=r"(r1) : "r"(a));
}
__device__ __forceinline__ void mma8(float* c, uint32_t a0, uint32_t a1, uint32_t a2, uint32_t a3,
                                     uint32_t b0, uint32_t b1) {
    asm volatile("mma.sync.aligned.m16n8k8.row.col.f32.tf32.tf32.f32 "
                 "{%0,%1,%2,%3}, {%4,%5,%6,%7}, {%8,%9}, {%0,%1,%2,%3};"
                 : "+f"(c[0]), "+f"(c[1]), "+f"(c[2]), "+f"(c[3])
                 : "r"(a0), "r"(a1), "r"(a2), "r"(a3), "r"(b0), "r"(b1));
}
__device__ __forceinline__ void cp16(uint32_t s, const void* g) {
    asm volatile("cp.async.cg.shared.global [%0], [%1], 16;" :: "r"(s), "l"(g));
}
__device__ __forceinline__ void cp_commit() {
    asm volatile("cp.async.commit_group;");
}
template <int N>
__device__ __forceinline__ void cp_wait() {
    asm volatile("cp.async.wait_group %0;" :: "n"(N));
}

// ---------------------------------------------------------------------------
// W transpose + tf32 convert: g_wt[p][n][k] = tf32(W_p[k][n]).
// ---------------------------------------------------------------------------
__global__ void wt_kernel(const float* __restrict__ Wq, const float* __restrict__ Wk,
                          const float* __restrict__ Wv)
{
    int i = blockIdx.x * blockDim.x + threadIdx.x;
    if (i >= 3 * DHEAD * DIN) return;
    int p = i / (DHEAD * DIN);
    int r = i % (DHEAD * DIN);
    int n = r / DIN, k = r % DIN;
    const float* W = (p == 0) ? Wq : (p == 1) ? Wk : Wv;
    g_wt[i] = cvt_tf32(W[k * DHEAD + n]);
}

// ---------------------------------------------------------------------------
// Projection GEMM (tf32 mma, fully async double-buffered): Y = X W + b
// CTA 128x128, 8 warps (4m x 2n), BK=32. Both X (raw fp32 used as tf32 — HW
// reads top 19 bits) and W staged via cp.async. One sync per k-step.
// ---------------------------------------------------------------------------
#define PBUF 4608   // 128*36 words per buffer

__global__ __launch_bounds__(256, 2) void proj_kernel(
    const float* __restrict__ Xq, const float* __restrict__ Xk, const float* __restrict__ Xv,
    const float* __restrict__ bq, const float* __restrict__ bk, const float* __restrict__ bv)
{
    extern __shared__ uint32_t psm[];
    uint32_t* Xs = psm;             // [2][128][36]
    uint32_t* Ws = psm + 2 * PBUF;  // [2][128][36]

    const int p = blockIdx.y;
    const float* X    = (p == 0) ? Xq : (p == 1) ? Xk : Xv;
    const float* bias = (p == 0) ? bq : (p == 1) ? bk : bv;
    const uint32_t* wt = g_wt + (size_t)p * DHEAD * DIN;

    const int row0 = blockIdx.x * 128;
    const int t    = threadIdx.x;
    const int wid  = t >> 5;
    const int lane = t & 31;
    const int g    = lane >> 2;
    const int t4   = lane & 3;
    const int wm   = (wid >> 1) * 32;
    const int wn   = (wid & 1) * 64;

    float acc[2][8][4];
#pragma unroll
    for (int i = 0; i < 2; i++)
#pragma unroll
        for (int j = 0; j < 8; j++)
#pragma unroll
            for (int q = 0; q < 4; q++) acc[i][j][q] = 0.f;

    const uint32_t xsb = sptr(Xs);
    const uint32_t wsb = sptr(Ws);
    const int arow = lane & 15, acol = (lane >> 4) << 2;
    const int brow = lane & 7,  bcol = ((lane >> 3) & 1) << 2;

    // preamble: issue k0=0 tiles into buffer 0
#pragma unroll
    for (int u = 0; u < 4; u++) {
        int f = t + (u << 8);
        int r = f >> 3, c = (f & 7) << 2;
        cp16(xsb + (r * 36 + c) * 4, X + (size_t)(row0 + r) * DIN + c);
        cp16(wsb + (r * 36 + c) * 4, wt + (size_t)r * DIN + c);
    }
    cp_commit();

    for (int k0 = 0; k0 < DIN; k0 += 32) {
        const int cur = (k0 >> 5) & 1;
        const int nxt = cur ^ 1;
        const bool has_next = (k0 + 32) < DIN;

        cp_wait<0>();
        __syncthreads();

        if (has_next) {
#pragma unroll
            for (int u = 0; u < 4; u++) {
                int f = t + (u << 8);
                int r = f >> 3, c = (f & 7) << 2;
                cp16(xsb + (nxt * PBUF + r * 36 + c) * 4,
                     X + (size_t)(row0 + r) * DIN + k0 + 32 + c);
                cp16(wsb + (nxt * PBUF + r * 36 + c) * 4,
                     wt + (size_t)r * DIN + k0 + 32 + c);
            }
            cp_commit();
        }

        const uint32_t xs0 = xsb + cur * PBUF * 4;
        const uint32_t ws0 = wsb + cur * PBUF * 4;
#pragma unroll
        for (int kk = 0; kk < 4; kk++) {
            uint32_t a[2][4];
#pragma unroll
            for (int mi = 0; mi < 2; mi++)
                ldsm_x4(a[mi][0], a[mi][1], a[mi][2], a[mi][3],
                        xs0 + ((wm + mi * 16 + arow) * 36 + kk * 8 + acol) * 4);
#pragma unroll
            for (int nt = 0; nt < 8; nt++) {
                uint32_t b0, b1;
                ldsm_x2(b0, b1, ws0 + ((wn + nt * 8 + brow) * 36 + kk * 8 + bcol) * 4);
                mma8(acc[0][nt], a[0][0], a[0][1], a[0][2], a[0][3], b0, b1);
                mma8(acc[1][nt], a[1][0], a[1][1], a[1][2], a[1][3], b0, b1);
            }
        }
    }

    const float sc = (p == 0) ? 0.088388347648318447f : 1.0f;
#pragma unroll
    for (int mi = 0; mi < 2; mi++) {
#pragma unroll
        for (int nt = 0; nt < 8; nt++) {
            int col = wn + nt * 8 + (t4 << 1);
#pragma unroll
            for (int half = 0; half < 2; half++) {
                int row = row0 + wm + mi * 16 + g + half * 8;
                float v0 = (acc[mi][nt][half * 2 + 0] + bias[col])     * sc;
                float v1 = (acc[mi][nt][half * 2 + 1] + bias[col + 1]) * sc;
                if (p == 2) {
                    int bb = row >> 11, ss = row & (SEQ - 1);
                    g_vt[(size_t)bb * DHEAD * SEQ + (size_t)col       * SEQ + ss] = cvt_tf32(v0);
                    g_vt[(size_t)bb * DHEAD * SEQ + (size_t)(col + 1) * SEQ + ss] = cvt_tf32(v1);
                } else {
                    uint32_t* out = (p == 0) ? g_q : g_k;
                    out[(size_t)row * DHEAD + col]     = cvt_tf32(v0);
                    out[(size_t)row * DHEAD + col + 1] = cvt_tf32(v1);
                }
            }
        }
    }
}

// ---------------------------------------------------------------------------
// Flash attention v4 (warp-owns-rows): 128 thr / 4 warps, 64 q-rows per CTA,
// grid (SEQ/64, BATCH) = 256 CTAs, 2/SM. Warp w owns q-rows 16w..16w+15 and
// all 32 keys of each tile:
//   - Q A-fragments in registers for the whole kernel (loaded once)
//   - softmax fully in registers (acc rows g,g+8 per thread; 2 shfl per row)
//   - P via warp-private smem patch (__syncwarp only)
//   - K,V double-buffered cp.async; ONE __syncthreads per iteration
// ---------------------------------------------------------------------------
#define KST 132            // K tile row stride (words); 528B = 33*16 aligned
#define VST 36             // V tile row stride
#define PST 36             // P patch row stride
#define KW  (32 * KST)     // 4224 words per K buffer
#define VW  (128 * VST)    // 4608 words per V buffer

__global__ __launch_bounds__(128, 2) void attn_kernel(float* __restrict__ O)
{
    extern __shared__ uint32_t smw[];
    uint32_t* Ks = smw;                    // [2][32][132]
    uint32_t* Vt = smw + 2 * KW;           // [2][128][36]
    uint32_t* Pw = smw + 2 * KW + 2 * VW;  // [4][16][36]

    const int b    = blockIdx.y;
    const int q0   = blockIdx.x * 64;
    const int t    = threadIdx.x;
    const int wid  = t >> 5;
    const int lane = t & 31;
    const int g    = lane >> 2;
    const int t4   = lane & 3;
    const int arow = lane & 15, acol = (lane >> 4) << 2;
    const int brow = lane & 7,  bcol = ((lane >> 3) & 1) << 2;

    const uint32_t* kg = g_k  + (size_t)b * SEQ * DHEAD;
    const uint32_t* vg = g_vt + (size_t)b * DHEAD * SEQ;
    const uint32_t* qg = g_q  + (size_t)(b * SEQ + q0) * DHEAD;

    const uint32_t ksb = sptr(Ks);
    const uint32_t vtb = sptr(Vt);
    uint32_t* Pmy = Pw + wid * 16 * PST;
    const uint32_t pwb = sptr(Pmy);

    // ---- stage Q through (unused yet) V area, pull A-frags into registers ----
    {
        uint32_t* Qst = Vt;   // 64*132 = 8448 <= 2*VW
#pragma unroll
        for (int u = 0; u < 16; u++) {
            int f = t + (u << 7);
            int r = f >> 5, c = (f & 31) << 2;
            *reinterpret_cast<uint4*>(Qst + r * KST + c) =
                *reinterpret_cast<const uint4*>(qg + (size_t)r * DHEAD + c);
        }
    }
    __syncthreads();
    uint32_t qf[16][4];
    {
        const uint32_t qstb = sptr(Vt);
#pragma unroll
        for (int ks = 0; ks < 16; ks++)
            ldsm_x4(qf[ks][0], qf[ks][1], qf[ks][2], qf[ks][3],
                    qstb + (((wid << 4) + arow) * KST + ks * 8 + acol) * 4);
    }
    __syncthreads();   // V area free again

    // ---- preamble: issue K0,V0 ----
#pragma unroll
    for (int u = 0; u < 8; u++) {
        int f = t + (u << 7);
        int r = f >> 5, c = (f & 31) << 2;
        cp16(ksb + (r * KST + c) * 4, kg + (size_t)r * DHEAD + c);
    }
#pragma unroll
    for (int u = 0; u < 8; u++) {
        int f = t + (u << 7);
        int rv = f >> 3, cv = (f & 7) << 2;
        cp16(vtb + (rv * VST + cv) * 4, vg + (size_t)rv * SEQ + cv);
    }
    cp_commit();

    float m0 = -1e30f, m1 = -1e30f, l0 = 0.f, l1 = 0.f;
    float o[16][4];
#pragma unroll
    for (int nt = 0; nt < 16; nt++)
#pragma unroll
        for (int q = 0; q < 4; q++) o[nt][q] = 0.f;

    for (int it = 0; it < SEQ / 32; it++) {
        const int cur = it & 1;
        cp_wait<0>();
        __syncthreads();

        if (it + 1 < SEQ / 32) {
            const int j1 = (it + 1) * 32;
            const int nb = cur ^ 1;
#pragma unroll
            for (int u = 0; u < 8; u++) {
                int f = t + (u << 7);
                int r = f >> 5, c = (f & 31) << 2;
                cp16(ksb + (nb * KW + r * KST + c) * 4, kg + (size_t)(j1 + r) * DHEAD + c);
            }
#pragma unroll
            for (int u = 0; u < 8; u++) {
                int f = t + (u << 7);
                int rv = f >> 3, cv = (f & 7) << 2;
                cp16(vtb + (nb * VW + rv * VST + cv) * 4, vg + (size_t)rv * SEQ + j1 + cv);
            }
            cp_commit();
        }

        // ---- pass 1: S[16q x 32k] per warp (Q from registers) ----
        const uint32_t ks0 = ksb + cur * KW * 4;
        float s[4][4];
#pragma unroll
        for (int nt = 0; nt < 4; nt++)
#pragma unroll
            for (int q = 0; q < 4; q++) s[nt][q] = 0.f;

#pragma unroll
        for (int ks = 0; ks < 16; ks++) {
#pragma unroll
            for (int nt = 0; nt < 4; nt++) {
                uint32_t b0, b1;
                ldsm_x2(b0, b1, ks0 + ((nt * 8 + brow) * KST + ks * 8 + bcol) * 4);
                mma8(s[nt], qf[ks][0], qf[ks][1], qf[ks][2], qf[ks][3], b0, b1);
            }
        }

        // ---- softmax in registers (rows g, g+8) ----
        float t0 = fmaxf(fmaxf(s[0][0], s[0][1]), fmaxf(s[1][0], s[1][1]));
        t0 = fmaxf(t0, fmaxf(fmaxf(s[2][0], s[2][1]), fmaxf(s[3][0], s[3][1])));
        float t1 = fmaxf(fmaxf(s[0][2], s[0][3]), fmaxf(s[1][2], s[1][3]));
        t1 = fmaxf(t1, fmaxf(fmaxf(s[2][2], s[2][3]), fmaxf(s[3][2], s[3][3])));
        t0 = fmaxf(t0, __shfl_xor_sync(0xffffffffu, t0, 1));
        t0 = fmaxf(t0, __shfl_xor_sync(0xffffffffu, t0, 2));
        t1 = fmaxf(t1, __shfl_xor_sync(0xffffffffu, t1, 1));
        t1 = fmaxf(t1, __shfl_xor_sync(0xffffffffu, t1, 2));

        const float mn0 = fmaxf(m0, t0), mn1 = fmaxf(m1, t1);
        const float a0 = __expf(m0 - mn0), a1 = __expf(m1 - mn1);
        m0 = mn0;  m1 = mn1;

        float ls0 = 0.f, ls1 = 0.f;
#pragma unroll
        for (int nt = 0; nt < 4; nt++) {
            float p00 = __expf(s[nt][0] - mn0);
            float p01 = __expf(s[nt][1] - mn0);
            float p10 = __expf(s[nt][2] - mn1);
            float p11 = __expf(s[nt][3] - mn1);
            ls0 += p00 + p01;
            ls1 += p10 + p11;
            uint2 w0 = {cvt_tf32(p00), cvt_tf32(p01)};
            uint2 w1 = {cvt_tf32(p10), cvt_tf32(p11)};
            *reinterpret_cast<uint2*>(Pmy + g * PST + nt * 8 + (t4 << 1))       = w0;
            *reinterpret_cast<uint2*>(Pmy + (g + 8) * PST + nt * 8 + (t4 << 1)) = w1;
        }
        ls0 += __shfl_xor_sync(0xffffffffu, ls0, 1);
        ls0 += __shfl_xor_sync(0xffffffffu, ls0, 2);
        ls1 += __shfl_xor_sync(0xffffffffu, ls1, 1);
        ls1 += __shfl_xor_sync(0xffffffffu, ls1, 2);
        l0 = l0 * a0 + ls0;
        l1 = l1 * a1 + ls1;
        __syncwarp();

        // ---- pass 2: O[16q x 128d] += P V (V from current buffer) ----
#pragma unroll
        for (int nt = 0; nt < 16; nt++) {
            o[nt][0] *= a0;  o[nt][1] *= a0;
            o[nt][2] *= a1;  o[nt][3] *= a1;
        }
        const uint32_t vt0 = vtb + cur * VW * 4;
#pragma unroll
        for (int kb = 0; kb < 4; kb++) {
            uint32_t pa0, pa1, pa2, pa3;
            ldsm_x4(pa0, pa1, pa2, pa3, pwb + (arow * PST + kb * 8 + acol) * 4);
#pragma unroll
            for (int nt = 0; nt < 16; nt++) {
                uint32_t b0, b1;
                ldsm_x2(b0, b1, vt0 + ((nt * 8 + brow) * VST + kb * 8 + bcol) * 4);
                mma8(o[nt], pa0, pa1, pa2, pa3, b0, b1);
            }
        }
        __syncwarp();   // P patch reads done before next iteration overwrites it
    }

    // ---- epilogue: O = acc / l (l per-thread, rows g and g+8) ----
    const float inv0 = 1.0f / l0;
    const float inv1 = 1.0f / l1;
    const int rbase = q0 + (wid << 4);
#pragma unroll
    for (int nt = 0; nt < 16; nt++) {
        int col = nt * 8 + (t4 << 1);
        float2 o0 = {o[nt][0] * inv0, o[nt][1] * inv0};
        float2 o1 = {o[nt][2] * inv1, o[nt][3] * inv1};
        *reinterpret_cast<float2*>(O + (size_t)(b * SEQ + rbase + g)     * DHEAD + col) = o0;
        *reinterpret_cast<float2*>(O + (size_t)(b * SEQ + rbase + g + 8) * DHEAD + col) = o1;
    }
}

// ---------------------------------------------------------------------------
extern "C" void kernel_launch(void* const* d_in, const int* in_sizes, int n_in,
                              void* d_out, int out_size)
{
    const float* query = (const float*)d_in[0];
    const float* key   = (const float*)d_in[1];
    const float* value = (const float*)d_in[2];
    const float* Wq    = (const float*)d_in[3];
    const float* bq    = (const float*)d_in[4];
    const float* Wk    = (const float*)d_in[5];
    const float* bk    = (const float*)d_in[6];
    const float* Wv    = (const float*)d_in[7];
    const float* bv    = (const float*)d_in[8];

    const int proj_smem = 4 * PBUF * 4;  // 73728
    cudaFuncSetAttribute(proj_kernel, cudaFuncAttributeMaxDynamicSharedMemorySize, proj_smem);

    const int attn_smem = (2 * KW + 2 * VW + 4 * 16 * PST) * 4;  // 79872
    cudaFuncSetAttribute(attn_kernel, cudaFuncAttributeMaxDynamicSharedMemorySize, attn_smem);

    wt_kernel<<<(3 * DHEAD * DIN + 255) / 256, 256>>>(Wq, Wk, Wv);

    dim3 pgrid(NROWS / 128, 3);
    proj_kernel<<<pgrid, 256, proj_smem>>>(query, key, value, bq, bk, bv);

    dim3 agrid(SEQ / 64, BATCH);
    attn_kernel<<<agrid, 128, attn_smem>>>((float*)d_out);
}